// round 1
// baseline (speedup 1.0000x reference)
#include <cuda_runtime.h>
#include <cuda_bf16.h>

// MotionLoss: per-row small-angle HTM chain + global MSE reduction.
// inputs  : [512,1024,18] f32   (d_in[0])
// targets : [512,1024, 7] f32   (d_in[1])
// out     : scalar f32 mean( ([err,disp] - targets[0:4])^2 )
//
// Strategy: HBM-bound streaming. Coalesced flat loads -> padded smem ->
// per-row compute -> block partial sums -> deterministic final reduce.

#define TPB 256
#define ROWS_PER_BLOCK 256
#define MAX_BLOCKS 8192

__device__ float g_partials[MAX_BLOCKS];

__global__ __launch_bounds__(TPB) void motion_loss_partial(
    const float* __restrict__ in, const float* __restrict__ tgt, int n_rows)
{
    __shared__ float s_in[ROWS_PER_BLOCK * 19];   // pad 18 -> 19 (coprime w/ 32 banks)
    __shared__ float s_tg[ROWS_PER_BLOCK * 7];    // stride 7 coprime w/ 32

    const int row0 = blockIdx.x * ROWS_PER_BLOCK;
    const int rows = min(ROWS_PER_BLOCK, n_rows - row0);

    // ---- coalesced staging: contiguous chunk, flat index ----
    const float* inb = in + (size_t)row0 * 18;
    const int tot_in = rows * 18;
    for (int g = threadIdx.x; g < tot_in; g += TPB) {
        int r = g / 18;
        int c = g - r * 18;
        s_in[r * 19 + c] = inb[g];
    }
    const float* tb = tgt + (size_t)row0 * 7;
    const int tot_tg = rows * 7;
    for (int g = threadIdx.x; g < tot_tg; g += TPB) {
        s_tg[g] = tb[g];
    }
    __syncthreads();

    float acc = 0.0f;
    if ((int)threadIdx.x < rows) {
        const float* v = &s_in[threadIdx.x * 19];
        const float* t = &s_tg[threadIdx.x * 7];

        // slices (MAG == 1 so no scaling)
        const float p0 = v[0], p1 = v[1], p2 = v[2];
        const float s00 = v[3], s01 = v[4];
        const float s10 = v[5], s11 = v[6];
        const float s20 = v[7], s21 = v[8];
        // ang rows: X=(9,10,11) Y=(12,13,14) Z=(15,16,17) as (ex,ey,ez)
        const float exX = v[9],  eyX = v[10], ezX = v[11];
        const float exY = v[12], eyY = v[13], ezY = v[14];
        const float exZ = v[15], eyZ = v[16], ezZ = v[17];

        const float x = t[4], y = t[5], z = t[6];

        // w = MX * (MY * (MZ * P)),  P = (x,y,z,1)
        // MZ: translation dZ = (s20, s21, p2)
        float ax = x - ezZ * y + eyZ * z + s20;
        float ay = ezZ * x + y - exZ * z + s21;
        float az = -eyZ * x + exZ * y + z + p2;
        // MY: dY = (s10, p1, s11)
        float bx = ax - ezY * ay + eyY * az + s10;
        float by = ezY * ax + ay - exY * az + p1;
        float bz = -eyY * ax + exY * ay + az + s11;
        // MX: dX = (p0, s00, s01)
        float cx = bx - ezX * by + eyX * bz + p0;
        float cy = ezX * bx + by - exX * bz + s00;
        float cz = -eyX * bx + exX * by + bz + s01;

        const float m1 = cx - x;
        const float m2 = cy - y;
        const float m3 = cz - z;
        const float err = sqrtf(m1 * m1 + m2 * m2 + m3 * m3 + 1e-12f);

        const float d0 = err - t[0];
        const float d1 = m1 - t[1];
        const float d2 = m2 - t[2];
        const float d3 = m3 - t[3];
        acc = d0 * d0 + d1 * d1 + d2 * d2 + d3 * d3;
    }

    // ---- block reduction: warp shuffle then smem ----
    #pragma unroll
    for (int off = 16; off > 0; off >>= 1)
        acc += __shfl_down_sync(0xFFFFFFFFu, acc, off);

    __shared__ float s_warp[TPB / 32];
    const int lane = threadIdx.x & 31;
    const int wid  = threadIdx.x >> 5;
    if (lane == 0) s_warp[wid] = acc;
    __syncthreads();
    if (wid == 0) {
        float a = (lane < TPB / 32) ? s_warp[lane] : 0.0f;
        #pragma unroll
        for (int off = 4; off > 0; off >>= 1)
            a += __shfl_down_sync(0xFFFFFFFFu, a, off);
        if (lane == 0) g_partials[blockIdx.x] = a;
    }
}

__global__ __launch_bounds__(TPB) void motion_loss_final(
    float* __restrict__ out, int n_blocks, int n_rows)
{
    // deterministic: fixed strided order per thread, tree reduce in double
    double sum = 0.0;
    for (int i = threadIdx.x; i < n_blocks; i += TPB)
        sum += (double)g_partials[i];

    __shared__ double s[TPB];
    s[threadIdx.x] = sum;
    __syncthreads();
    #pragma unroll
    for (int off = TPB / 2; off > 0; off >>= 1) {
        if ((int)threadIdx.x < off) s[threadIdx.x] += s[threadIdx.x + off];
        __syncthreads();
    }
    if (threadIdx.x == 0)
        out[0] = (float)(s[0] / ((double)n_rows * 4.0));
}

extern "C" void kernel_launch(void* const* d_in, const int* in_sizes, int n_in,
                              void* d_out, int out_size)
{
    const float* inputs  = (const float*)d_in[0];
    const float* targets = (const float*)d_in[1];
    float* out = (float*)d_out;

    const int n_rows = in_sizes[0] / 18;            // 524288
    const int n_blocks = (n_rows + ROWS_PER_BLOCK - 1) / ROWS_PER_BLOCK;  // 2048

    motion_loss_partial<<<n_blocks, TPB>>>(inputs, targets, n_rows);
    motion_loss_final<<<1, TPB>>>(out, n_blocks, n_rows);
}